// round 1
// baseline (speedup 1.0000x reference)
#include <cuda_runtime.h>
#include <math.h>

#define N_PTS  32768
#define N_DIM  8
#define OP1    25      // order + 1
#define N_PERM 32
#define KP     13      // ceil(26/2) f32x2 pairs per vector
#define KROW   14      // padded pairs per smem weight row (112B, 16B-aligned rows)

typedef unsigned long long ull;

struct Sc2   { float v[28]; };
struct Binom { float b[28]; };

// Bernstein basis scratch: layout [(d*KP + kk)*N_PTS + n], float2 = (B[2kk], B[2kk+1])
__device__ float2 g_Bt[N_DIM * KP * N_PTS];

// ---------------- packed f32x2 helpers ----------------
__device__ __forceinline__ ull pk2(float l, float h) {
    ull r; asm("mov.b64 %0, {%1, %2};" : "=l"(r) : "f"(l), "f"(h)); return r;
}
__device__ __forceinline__ float lo2(ull a) {
    float l, h; asm("mov.b64 {%0, %1}, %2;" : "=f"(l), "=f"(h) : "l"(a)); return l;
}
__device__ __forceinline__ float hi2(ull a) {
    float l, h; asm("mov.b64 {%0, %1}, %2;" : "=f"(l), "=f"(h) : "l"(a)); return h;
}
__device__ __forceinline__ ull dup2(float x) { return pk2(x, x); }
__device__ __forceinline__ ull fma2(ull a, ull b, ull c) {
    ull d; asm("fma.rn.f32x2 %0, %1, %2, %3;" : "=l"(d) : "l"(a), "l"(b), "l"(c)); return d;
}
__device__ __forceinline__ ull mul2(ull a, ull b) {
    ull d; asm("mul.rn.f32x2 %0, %1, %2;" : "=l"(d) : "l"(a), "l"(b)); return d;
}
__device__ __forceinline__ ull add2(ull a, ull b) {
    ull d; asm("add.rn.f32x2 %0, %1, %2;" : "=l"(d) : "l"(a), "l"(b)); return d;
}

// ---------------- pre-kernel: Bernstein basis + output zero-init ----------------
__global__ void bern_prep_kernel(const float* __restrict__ X,
                                 float* __restrict__ out, Binom bn)
{
    const int idx = blockIdx.x * blockDim.x + threadIdx.x;   // over N_DIM*N_PTS
    if (idx < 2 * N_PTS) out[idx] = 0.0f;                    // zero d_out (poisoned)
    if (idx >= N_DIM * N_PTS) return;
    const int d = idx >> 15;            // idx / 32768
    const int n = idx & (N_PTS - 1);

    const float x = X[n * N_DIM + d];
    const float q = 1.0f - x;

    float xpk[OP1];
    float xp = 1.0f;
    #pragma unroll
    for (int k = 0; k < OP1; k++) { xpk[k] = xp; xp *= x; }

    float B[26];
    float qp = 1.0f;
    #pragma unroll
    for (int k = OP1 - 1; k >= 0; k--) { B[k] = bn.b[k] * xpk[k] * qp; qp *= q; }
    B[25] = 0.0f;

    #pragma unroll
    for (int kk = 0; kk < KP; kk++)
        g_Bt[(d * KP + kk) * N_PTS + n] = make_float2(B[2*kk], B[2*kk + 1]);
}

// ---------------- main kernel ----------------
__global__ __launch_bounds__(256, 1)
void bern_main_kernel(const int*   __restrict__ perm,
                      const float* __restrict__ mw0,
                      const float* __restrict__ mwr,
                      const float* __restrict__ vw0,
                      const float* __restrict__ vwr,
                      const float* __restrict__ postp,
                      float*       __restrict__ out,
                      Sc2 sc2)
{
    __shared__ alignas(16) ull sWm[7 * 25 * KROW];
    __shared__ alignas(16) ull sWv[7 * 25 * KROW];
    __shared__ alignas(16) ull sw0m[KROW];
    __shared__ alignas(16) ull sw0v[KROW];
    __shared__ int   sperm[8];
    __shared__ float sinvpp;

    const int p   = blockIdx.y;
    const int tid = threadIdx.x;

    // Cooperative weight load: mean copied, var = exp(w)*sc2[k]; pad k>=25 with 0.
    {
        float* fWm = (float*)sWm;
        float* fWv = (float*)sWv;
        for (int t = tid; t < 7 * 25 * 2 * KROW; t += 256) {
            const int k  = t % (2 * KROW);
            const int rj = t / (2 * KROW);
            const int j  = rj % 25;
            const int s  = rj / 25;
            float m = 0.0f, v = 0.0f;
            if (k < OP1) {
                const int gi = ((s * N_PERM + p) * OP1 + j) * OP1 + k;
                m = mwr[gi];
                v = expf(vwr[gi]) * sc2.v[k];
            }
            fWm[t] = m;
            fWv[t] = v;
        }
        if (tid < 2 * KROW) {
            float m = 0.0f, v = 0.0f;
            if (tid < OP1) {
                m = mw0[p * OP1 + tid];
                v = expf(vw0[p * OP1 + tid]) * sc2.v[tid];
            }
            ((float*)sw0m)[tid] = m;
            ((float*)sw0v)[tid] = v;
        }
        if (tid < 8)  sperm[tid] = perm[p * 8 + tid];
        if (tid == 0) sinvpp = 1.0f / postp[p];
    }
    __syncthreads();

    const int n = blockIdx.x * 256 + tid;

    ull vm[KP], vv[KP];

    // stage 0: row-vector times basis
    {
        const int d0 = sperm[0];
        const float2* bp = g_Bt + (size_t)d0 * KP * N_PTS + n;
        #pragma unroll
        for (int kk = 0; kk < KP; kk++) {
            const ull b = *(const ull*)(bp + (size_t)kk * N_PTS);
            vm[kk] = mul2(sw0m[kk], b);
            vv[kk] = mul2(mul2(sw0v[kk], b), b);
        }
    }

    // stages 1..7: v <- (v @ W) * B   (rolled over s to stay inside I$)
    #pragma unroll 1
    for (int s = 0; s < 7; s++) {
        const int d = sperm[s + 1];
        const float2* bp = g_Bt + (size_t)d * KP * N_PTS + n;
        ull b[KP];
        #pragma unroll
        for (int kk = 0; kk < KP; kk++)
            b[kk] = *(const ull*)(bp + (size_t)kk * N_PTS);

        ull am[KP], av[KP];
        #pragma unroll
        for (int kk = 0; kk < KP; kk++) { am[kk] = 0ULL; av[kk] = 0ULL; }

        const ull* baseM = sWm + s * 25 * KROW;
        const ull* baseV = sWv + s * 25 * KROW;

        #pragma unroll
        for (int j = 0; j < 25; j++) {
            const float mj = (j & 1) ? hi2(vm[j >> 1]) : lo2(vm[j >> 1]);
            const float vj = (j & 1) ? hi2(vv[j >> 1]) : lo2(vv[j >> 1]);
            const ull mj2 = dup2(mj);
            const ull vj2 = dup2(vj);
            const ull* rm = baseM + j * KROW;
            const ull* rv = baseV + j * KROW;
            #pragma unroll
            for (int h = 0; h < 7; h++) {
                const ulonglong2 wm = *(const ulonglong2*)(rm + 2 * h);
                const ulonglong2 wv = *(const ulonglong2*)(rv + 2 * h);
                am[2*h] = fma2(mj2, wm.x, am[2*h]);
                av[2*h] = fma2(vj2, wv.x, av[2*h]);
                if (2*h + 1 < KP) {
                    am[2*h + 1] = fma2(mj2, wm.y, am[2*h + 1]);
                    av[2*h + 1] = fma2(vj2, wv.y, av[2*h + 1]);
                }
            }
        }

        #pragma unroll
        for (int kk = 0; kk < KP; kk++) {
            vm[kk] = mul2(am[kk], b[kk]);
            const ull bb = mul2(b[kk], b[kk]);
            vv[kk] = mul2(av[kk], bb);
        }
    }

    // reduce over k, then over p via atomics
    ull sm = vm[0], sv = vv[0];
    #pragma unroll
    for (int kk = 1; kk < KP; kk++) { sm = add2(sm, vm[kk]); sv = add2(sv, vv[kk]); }
    const float fmean = lo2(sm) + hi2(sm);
    const float fvar  = (lo2(sv) + hi2(sv)) * sinvpp;

    atomicAdd(out + 2 * n,     fmean);
    atomicAdd(out + 2 * n + 1, fvar);
}

// ---------------- host: sc2 = inv(B(I)^2) @ ones in double ----------------
static void compute_binom_d(double* bn) {
    bn[0] = 1.0;
    for (int k = 0; k < 24; k++) bn[k + 1] = bn[k] * (double)(24 - k) / (double)(k + 1);
}

static void compute_sc2_d(const double* bn, double* y) {
    double A[25][26];
    for (int i = 0; i < 25; i++) {
        const double t = (double)i / 24.0;
        const double q = 1.0 - t;
        double xp[25], qp[25];
        xp[0] = 1.0; for (int k = 1; k < 25; k++) xp[k] = xp[k - 1] * t;
        qp[0] = 1.0; for (int k = 1; k < 25; k++) qp[k] = qp[k - 1] * q;
        for (int k = 0; k < 25; k++) {
            const double B = bn[k] * xp[k] * qp[24 - k];
            A[i][k] = B * B;
        }
        A[i][25] = 1.0;   // rhs = ones
    }
    // Gauss-Jordan with partial pivoting
    for (int c = 0; c < 25; c++) {
        int piv = c;
        for (int r = c + 1; r < 25; r++)
            if (fabs(A[r][c]) > fabs(A[piv][c])) piv = r;
        if (piv != c)
            for (int k = c; k < 26; k++) { double tmp = A[c][k]; A[c][k] = A[piv][k]; A[piv][k] = tmp; }
        const double inv = 1.0 / A[c][c];
        for (int r = 0; r < 25; r++) {
            if (r == c) continue;
            const double f = A[r][c] * inv;
            for (int k = c; k < 26; k++) A[r][k] -= f * A[c][k];
        }
    }
    for (int i = 0; i < 25; i++) y[i] = A[i][25] / A[i][i];
}

extern "C" void kernel_launch(void* const* d_in, const int* in_sizes, int n_in,
                              void* d_out, int out_size)
{
    const float* X    = (const float*)d_in[0];   // Xnew      (N, 8)
    const int*   perm = (const int*)  d_in[1];   // perm      (32, 8)
    const float* mw0  = (const float*)d_in[2];   // meanw0    (32, 1, 25)
    const float* mwr  = (const float*)d_in[3];   // meanw_rest(7, 32, 25, 25)
    const float* vw0  = (const float*)d_in[4];   // varw0     (32, 1, 25)
    const float* vwr  = (const float*)d_in[5];   // varw_rest (7, 32, 25, 25)
    const float* pp   = (const float*)d_in[6];   // post_prec (32,)
    float* out = (float*)d_out;                  // (N, 2) float32

    double bn_d[25], sc2_d[25];
    compute_binom_d(bn_d);
    compute_sc2_d(bn_d, sc2_d);

    Binom bn = {};
    Sc2   sc = {};
    for (int k = 0; k < 25; k++) {
        bn.b[k] = (float)bn_d[k];
        sc.v[k] = (float)sc2_d[k];
    }

    bern_prep_kernel<<<(N_DIM * N_PTS) / 256, 256>>>(X, out, bn);

    dim3 grid(N_PTS / 256, N_PERM);
    bern_main_kernel<<<grid, 256>>>(perm, mw0, mwr, vw0, vwr, pp, out, sc);
}

// round 2
// speedup vs baseline: 1.3487x; 1.3487x over previous
#include <cuda_runtime.h>
#include <math.h>

#define N_PTS  32768
#define N_DIM  8
#define OP1    25      // order + 1
#define N_PERM 32
#define KP     13      // ceil(26/2) f32x2 pairs per vector
#define KROW   14      // padded pairs per smem weight row (112B, 16B-aligned rows)

typedef unsigned long long ull;

struct Sc2   { float v[28]; };
struct Binom { float b[28]; };

// Bernstein basis scratch: layout [(d*KP + kk)*N_PTS + n], float2 = (B[2kk], B[2kk+1])
__device__ float2 g_Bt[N_DIM * KP * N_PTS];

// ---------------- packed f32x2 helpers ----------------
__device__ __forceinline__ ull pk2(float l, float h) {
    ull r; asm("mov.b64 %0, {%1, %2};" : "=l"(r) : "f"(l), "f"(h)); return r;
}
__device__ __forceinline__ float lo2(ull a) {
    float l, h; asm("mov.b64 {%0, %1}, %2;" : "=f"(l), "=f"(h) : "l"(a)); return l;
}
__device__ __forceinline__ float hi2(ull a) {
    float l, h; asm("mov.b64 {%0, %1}, %2;" : "=f"(l), "=f"(h) : "l"(a)); return h;
}
__device__ __forceinline__ ull dup2(float x) { return pk2(x, x); }
__device__ __forceinline__ ull fma2(ull a, ull b, ull c) {
    ull d; asm("fma.rn.f32x2 %0, %1, %2, %3;" : "=l"(d) : "l"(a), "l"(b), "l"(c)); return d;
}
__device__ __forceinline__ ull mul2(ull a, ull b) {
    ull d; asm("mul.rn.f32x2 %0, %1, %2;" : "=l"(d) : "l"(a), "l"(b)); return d;
}
__device__ __forceinline__ ull add2(ull a, ull b) {
    ull d; asm("add.rn.f32x2 %0, %1, %2;" : "=l"(d) : "l"(a), "l"(b)); return d;
}

// ---------------- pre-kernel: Bernstein basis + output zero-init ----------------
__global__ void bern_prep_kernel(const float* __restrict__ X,
                                 float* __restrict__ out, Binom bn)
{
    const int idx = blockIdx.x * blockDim.x + threadIdx.x;   // over N_DIM*N_PTS
    if (idx < 2 * N_PTS) out[idx] = 0.0f;                    // zero d_out (poisoned)
    if (idx >= N_DIM * N_PTS) return;
    const int d = idx >> 15;            // idx / 32768
    const int n = idx & (N_PTS - 1);

    const float x = X[n * N_DIM + d];
    const float q = 1.0f - x;

    float xpk[OP1];
    float xp = 1.0f;
    #pragma unroll
    for (int k = 0; k < OP1; k++) { xpk[k] = xp; xp *= x; }

    float B[26];
    float qp = 1.0f;
    #pragma unroll
    for (int k = OP1 - 1; k >= 0; k--) { B[k] = bn.b[k] * xpk[k] * qp; qp *= q; }
    B[25] = 0.0f;

    #pragma unroll
    for (int kk = 0; kk < KP; kk++)
        g_Bt[(d * KP + kk) * N_PTS + n] = make_float2(B[2*kk], B[2*kk + 1]);
}

// ---------------- main kernel: one chain (mean or var) per block ----------------
// VAR=0: v <- (v @ W) * B                 , out col 0, weights = meanw
// VAR=1: v <- (v @ (exp(W)*sc2)) * B*B    , out col 1 (scaled 1/post_prec)
template<int VAR>
__global__ __launch_bounds__(256, 2)
void bern_chain_kernel(const int*   __restrict__ perm,
                       const float* __restrict__ w0g,
                       const float* __restrict__ wrg,
                       const float* __restrict__ postp,
                       float*       __restrict__ out,
                       Sc2 sc2)
{
    __shared__ alignas(16) ull sW[7 * 25 * KROW];
    __shared__ alignas(16) ull sw0[KROW];
    __shared__ int   sperm[8];
    __shared__ float sscale;

    const int p   = blockIdx.y;
    const int tid = threadIdx.x;

    // Cooperative weight load; var chain applies exp(w)*sc2[k]; pad k>=25 with 0.
    {
        float* fW = (float*)sW;
        for (int t = tid; t < 7 * 25 * 2 * KROW; t += 256) {
            const int k  = t % (2 * KROW);
            const int rj = t / (2 * KROW);
            const int j  = rj % 25;
            const int s  = rj / 25;
            float w = 0.0f;
            if (k < OP1) {
                const int gi = ((s * N_PERM + p) * OP1 + j) * OP1 + k;
                w = VAR ? expf(wrg[gi]) * sc2.v[k] : wrg[gi];
            }
            fW[t] = w;
        }
        if (tid < 2 * KROW) {
            float w = 0.0f;
            if (tid < OP1)
                w = VAR ? expf(w0g[p * OP1 + tid]) * sc2.v[tid] : w0g[p * OP1 + tid];
            ((float*)sw0)[tid] = w;
        }
        if (tid < 8)  sperm[tid] = perm[p * 8 + tid];
        if (tid == 0) sscale = VAR ? 1.0f / postp[p] : 1.0f;
    }
    __syncthreads();

    const int n = blockIdx.x * 256 + tid;

    ull v[KP];

    // stage 0
    {
        const int d0 = sperm[0];
        const float2* bp = g_Bt + (size_t)d0 * KP * N_PTS + n;
        #pragma unroll
        for (int kk = 0; kk < KP; kk++) {
            const ull b = *(const ull*)(bp + (size_t)kk * N_PTS);
            if (VAR) v[kk] = mul2(mul2(sw0[kk], b), b);
            else     v[kk] = mul2(sw0[kk], b);
        }
    }

    // stages 1..7 (rolled over s to stay inside I$)
    #pragma unroll 1
    for (int s = 0; s < 7; s++) {
        const int d = sperm[s + 1];
        const float2* bp = g_Bt + (size_t)d * KP * N_PTS + n;
        ull b[KP];
        #pragma unroll
        for (int kk = 0; kk < KP; kk++)
            b[kk] = *(const ull*)(bp + (size_t)kk * N_PTS);

        ull acc[KP];
        #pragma unroll
        for (int kk = 0; kk < KP; kk++) acc[kk] = 0ULL;

        const ull* base = sW + s * 25 * KROW;

        #pragma unroll
        for (int j = 0; j < 25; j++) {
            const float vj = (j & 1) ? hi2(v[j >> 1]) : lo2(v[j >> 1]);
            const ull vj2 = dup2(vj);
            const ull* rw = base + j * KROW;
            #pragma unroll
            for (int h = 0; h < 7; h++) {
                const ulonglong2 w = *(const ulonglong2*)(rw + 2 * h);
                acc[2*h] = fma2(vj2, w.x, acc[2*h]);
                if (2*h + 1 < KP)
                    acc[2*h + 1] = fma2(vj2, w.y, acc[2*h + 1]);
            }
        }

        #pragma unroll
        for (int kk = 0; kk < KP; kk++) {
            if (VAR) v[kk] = mul2(acc[kk], mul2(b[kk], b[kk]));
            else     v[kk] = mul2(acc[kk], b[kk]);
        }
    }

    // reduce over k, then over p via atomics
    ull sm = v[0];
    #pragma unroll
    for (int kk = 1; kk < KP; kk++) sm = add2(sm, v[kk]);
    const float r = (lo2(sm) + hi2(sm)) * sscale;

    atomicAdd(out + 2 * n + VAR, r);
}

// ---------------- host: sc2 = inv(B(I)^2) @ ones in double ----------------
static void compute_binom_d(double* bn) {
    bn[0] = 1.0;
    for (int k = 0; k < 24; k++) bn[k + 1] = bn[k] * (double)(24 - k) / (double)(k + 1);
}

static void compute_sc2_d(const double* bn, double* y) {
    double A[25][26];
    for (int i = 0; i < 25; i++) {
        const double t = (double)i / 24.0;
        const double q = 1.0 - t;
        double xp[25], qp[25];
        xp[0] = 1.0; for (int k = 1; k < 25; k++) xp[k] = xp[k - 1] * t;
        qp[0] = 1.0; for (int k = 1; k < 25; k++) qp[k] = qp[k - 1] * q;
        for (int k = 0; k < 25; k++) {
            const double B = bn[k] * xp[k] * qp[24 - k];
            A[i][k] = B * B;
        }
        A[i][25] = 1.0;   // rhs = ones
    }
    for (int c = 0; c < 25; c++) {
        int piv = c;
        for (int r = c + 1; r < 25; r++)
            if (fabs(A[r][c]) > fabs(A[piv][c])) piv = r;
        if (piv != c)
            for (int k = c; k < 26; k++) { double tmp = A[c][k]; A[c][k] = A[piv][k]; A[piv][k] = tmp; }
        const double inv = 1.0 / A[c][c];
        for (int r = 0; r < 25; r++) {
            if (r == c) continue;
            const double f = A[r][c] * inv;
            for (int k = c; k < 26; k++) A[r][k] -= f * A[c][k];
        }
    }
    for (int i = 0; i < 25; i++) y[i] = A[i][25] / A[i][i];
}

extern "C" void kernel_launch(void* const* d_in, const int* in_sizes, int n_in,
                              void* d_out, int out_size)
{
    const float* X    = (const float*)d_in[0];   // Xnew      (N, 8)
    const int*   perm = (const int*)  d_in[1];   // perm      (32, 8)
    const float* mw0  = (const float*)d_in[2];   // meanw0    (32, 1, 25)
    const float* mwr  = (const float*)d_in[3];   // meanw_rest(7, 32, 25, 25)
    const float* vw0  = (const float*)d_in[4];   // varw0     (32, 1, 25)
    const float* vwr  = (const float*)d_in[5];   // varw_rest (7, 32, 25, 25)
    const float* pp   = (const float*)d_in[6];   // post_prec (32,)
    float* out = (float*)d_out;                  // (N, 2) float32

    double bn_d[25], sc2_d[25];
    compute_binom_d(bn_d);
    compute_sc2_d(bn_d, sc2_d);

    Binom bn = {};
    Sc2   sc = {};
    for (int k = 0; k < 25; k++) {
        bn.b[k] = (float)bn_d[k];
        sc.v[k] = (float)sc2_d[k];
    }

    bern_prep_kernel<<<(N_DIM * N_PTS) / 256, 256>>>(X, out, bn);

    dim3 grid(N_PTS / 256, N_PERM);
    bern_chain_kernel<0><<<grid, 256>>>(perm, mw0, mwr, pp, out, sc);
    bern_chain_kernel<1><<<grid, 256>>>(perm, vw0, vwr, pp, out, sc);
}

// round 4
// speedup vs baseline: 1.6846x; 1.2491x over previous
#include <cuda_runtime.h>
#include <math.h>

#define N_PTS  32768
#define N_DIM  8
#define OP1    25      // order + 1
#define N_PERM 32
#define KP     13      // ceil(26/2) f32x2 pairs per vector
#define KROW   14      // padded pairs per smem weight row (112B, 16B-aligned rows)

typedef unsigned long long ull;

struct Sc2   { float v[28]; };
struct Binom { float b[28]; };

// Bernstein basis scratch: layout [(d*KP + kk)*N_PTS + n], float2 = (B[2kk], B[2kk+1])
__device__ float2 g_Bt[N_DIM * KP * N_PTS];

// ---------------- packed f32x2 helpers ----------------
__device__ __forceinline__ ull pk2(float l, float h) {
    ull r; asm("mov.b64 %0, {%1, %2};" : "=l"(r) : "f"(l), "f"(h)); return r;
}
__device__ __forceinline__ float lo2(ull a) {
    float l, h; asm("mov.b64 {%0, %1}, %2;" : "=f"(l), "=f"(h) : "l"(a)); return l;
}
__device__ __forceinline__ float hi2(ull a) {
    float l, h; asm("mov.b64 {%0, %1}, %2;" : "=f"(l), "=f"(h) : "l"(a)); return h;
}
__device__ __forceinline__ ull dup2(float x) { return pk2(x, x); }
__device__ __forceinline__ ull fma2(ull a, ull b, ull c) {
    ull d; asm("fma.rn.f32x2 %0, %1, %2, %3;" : "=l"(d) : "l"(a), "l"(b), "l"(c)); return d;
}
__device__ __forceinline__ ull mul2(ull a, ull b) {
    ull d; asm("mul.rn.f32x2 %0, %1, %2;" : "=l"(d) : "l"(a), "l"(b)); return d;
}
__device__ __forceinline__ ull add2(ull a, ull b) {
    ull d; asm("add.rn.f32x2 %0, %1, %2;" : "=l"(d) : "l"(a), "l"(b)); return d;
}

// ---------------- pre-kernel: Bernstein basis + output zero-init ----------------
__global__ void bern_prep_kernel(const float* __restrict__ X,
                                 float* __restrict__ out, Binom bn)
{
    const int idx = blockIdx.x * blockDim.x + threadIdx.x;   // over N_DIM*N_PTS
    if (idx < 2 * N_PTS) out[idx] = 0.0f;                    // zero d_out (poisoned)
    if (idx >= N_DIM * N_PTS) return;
    const int d = idx >> 15;            // idx / 32768
    const int n = idx & (N_PTS - 1);

    const float x = X[n * N_DIM + d];
    const float q = 1.0f - x;

    float xpk[OP1];
    float xp = 1.0f;
    #pragma unroll
    for (int k = 0; k < OP1; k++) { xpk[k] = xp; xp *= x; }

    float B[26];
    float qp = 1.0f;
    #pragma unroll
    for (int k = OP1 - 1; k >= 0; k--) { B[k] = bn.b[k] * xpk[k] * qp; qp *= q; }
    B[25] = 0.0f;

    #pragma unroll
    for (int kk = 0; kk < KP; kk++)
        g_Bt[(d * KP + kk) * N_PTS + n] = make_float2(B[2*kk], B[2*kk + 1]);
}

// ---------------- main kernel: one chain (mean or var) per block, 2 pts/thread ----
// blockIdx.z == 0: mean chain   v <- (v @ W) * B              -> out col 0
// blockIdx.z == 1: var chain    v <- (v @ (exp(W)*sc2)) * B^2 -> out col 1 (/post_prec)
__global__ __launch_bounds__(128, 4)
void bern_chain_kernel(const int*   __restrict__ perm,
                       const float* __restrict__ mw0,
                       const float* __restrict__ mwr,
                       const float* __restrict__ vw0,
                       const float* __restrict__ vwr,
                       const float* __restrict__ postp,
                       float*       __restrict__ out,
                       Sc2 sc2)
{
    __shared__ alignas(16) ull sW[7 * 25 * KROW];
    __shared__ alignas(16) ull sw0[KROW];
    __shared__ int   sperm[8];
    __shared__ float sscale;

    const int p   = blockIdx.y;
    const int VAR = blockIdx.z;
    const int tid = threadIdx.x;

    const float* __restrict__ w0g = VAR ? vw0 : mw0;
    const float* __restrict__ wrg = VAR ? vwr : mwr;

    // Cooperative weight load; var chain applies exp(w)*sc2[k]; pad k>=25 with 0.
    {
        float* fW = (float*)sW;
        for (int t = tid; t < 7 * 25 * 2 * KROW; t += 128) {
            const int k  = t % (2 * KROW);
            const int rj = t / (2 * KROW);
            const int j  = rj % 25;
            const int s  = rj / 25;
            float w = 0.0f;
            if (k < OP1) {
                const int gi = ((s * N_PERM + p) * OP1 + j) * OP1 + k;
                w = VAR ? expf(wrg[gi]) * sc2.v[k] : wrg[gi];
            }
            fW[t] = w;
        }
        if (tid < 2 * KROW) {
            float w = 0.0f;
            if (tid < OP1)
                w = VAR ? expf(w0g[p * OP1 + tid]) * sc2.v[tid] : w0g[p * OP1 + tid];
            ((float*)sw0)[tid] = w;
        }
        if (tid < 8)  sperm[tid] = perm[p * 8 + tid];
        if (tid == 0) sscale = VAR ? 1.0f / postp[p] : 1.0f;
    }
    __syncthreads();

    const int n0 = blockIdx.x * 256 + tid;   // point 0
    const int n1 = n0 + 128;                 // point 1

    ull v0[KP], v1[KP];

    // stage 0
    {
        const int d0 = sperm[0];
        const float2* bp = g_Bt + (size_t)d0 * KP * N_PTS;
        #pragma unroll
        for (int kk = 0; kk < KP; kk++) {
            const ull b0 = *(const ull*)(bp + (size_t)kk * N_PTS + n0);
            const ull b1 = *(const ull*)(bp + (size_t)kk * N_PTS + n1);
            if (VAR) {
                v0[kk] = mul2(mul2(sw0[kk], b0), b0);
                v1[kk] = mul2(mul2(sw0[kk], b1), b1);
            } else {
                v0[kk] = mul2(sw0[kk], b0);
                v1[kk] = mul2(sw0[kk], b1);
            }
        }
    }

    // stages 1..7 (rolled over s to stay inside I$)
    #pragma unroll 1
    for (int s = 0; s < 7; s++) {
        const int d = sperm[s + 1];
        const float2* bp = g_Bt + (size_t)d * KP * N_PTS;

        ull acc0[KP], acc1[KP];
        #pragma unroll
        for (int kk = 0; kk < KP; kk++) { acc0[kk] = 0ULL; acc1[kk] = 0ULL; }

        const ull* base = sW + s * 25 * KROW;

        #pragma unroll
        for (int j = 0; j < 25; j++) {
            const float a0 = (j & 1) ? hi2(v0[j >> 1]) : lo2(v0[j >> 1]);
            const float a1 = (j & 1) ? hi2(v1[j >> 1]) : lo2(v1[j >> 1]);
            const ull vj0 = dup2(a0);
            const ull vj1 = dup2(a1);
            const ull* rw = base + j * KROW;
            #pragma unroll
            for (int h = 0; h < 7; h++) {
                const ulonglong2 w = *(const ulonglong2*)(rw + 2 * h);
                acc0[2*h] = fma2(vj0, w.x, acc0[2*h]);
                acc1[2*h] = fma2(vj1, w.x, acc1[2*h]);
                if (2*h + 1 < KP) {
                    acc0[2*h + 1] = fma2(vj0, w.y, acc0[2*h + 1]);
                    acc1[2*h + 1] = fma2(vj1, w.y, acc1[2*h + 1]);
                }
            }
        }

        // apply basis (streamed: b registers consumed immediately to limit pressure)
        #pragma unroll
        for (int kk = 0; kk < KP; kk++) {
            const ull b0 = *(const ull*)(bp + (size_t)kk * N_PTS + n0);
            const ull b1 = *(const ull*)(bp + (size_t)kk * N_PTS + n1);
            if (VAR) {
                v0[kk] = mul2(acc0[kk], mul2(b0, b0));
                v1[kk] = mul2(acc1[kk], mul2(b1, b1));
            } else {
                v0[kk] = mul2(acc0[kk], b0);
                v1[kk] = mul2(acc1[kk], b1);
            }
        }
    }

    // reduce over k, then over p via atomics
    ull s0 = v0[0], s1 = v1[0];
    #pragma unroll
    for (int kk = 1; kk < KP; kk++) { s0 = add2(s0, v0[kk]); s1 = add2(s1, v1[kk]); }
    const float r0 = (lo2(s0) + hi2(s0)) * sscale;
    const float r1 = (lo2(s1) + hi2(s1)) * sscale;

    atomicAdd(out + 2 * n0 + VAR, r0);
    atomicAdd(out + 2 * n1 + VAR, r1);
}

// ---------------- host: sc2 = inv(B(I)^2) @ ones in double ----------------
static void compute_binom_d(double* bn) {
    bn[0] = 1.0;
    for (int k = 0; k < 24; k++) bn[k + 1] = bn[k] * (double)(24 - k) / (double)(k + 1);
}

static void compute_sc2_d(const double* bn, double* y) {
    double A[25][26];
    for (int i = 0; i < 25; i++) {
        const double t = (double)i / 24.0;
        const double q = 1.0 - t;
        double xp[25], qp[25];
        xp[0] = 1.0; for (int k = 1; k < 25; k++) xp[k] = xp[k - 1] * t;
        qp[0] = 1.0; for (int k = 1; k < 25; k++) qp[k] = qp[k - 1] * q;
        for (int k = 0; k < 25; k++) {
            const double B = bn[k] * xp[k] * qp[24 - k];
            A[i][k] = B * B;
        }
        A[i][25] = 1.0;   // rhs = ones
    }
    for (int c = 0; c < 25; c++) {
        int piv = c;
        for (int r = c + 1; r < 25; r++)
            if (fabs(A[r][c]) > fabs(A[piv][c])) piv = r;
        if (piv != c)
            for (int k = c; k < 26; k++) { double tmp = A[c][k]; A[c][k] = A[piv][k]; A[piv][k] = tmp; }
        const double inv = 1.0 / A[c][c];
        for (int r = 0; r < 25; r++) {
            if (r == c) continue;
            const double f = A[r][c] * inv;
            for (int k = c; k < 26; k++) A[r][k] -= f * A[c][k];
        }
    }
    for (int i = 0; i < 25; i++) y[i] = A[i][25] / A[i][i];
}

extern "C" void kernel_launch(void* const* d_in, const int* in_sizes, int n_in,
                              void* d_out, int out_size)
{
    const float* X    = (const float*)d_in[0];   // Xnew      (N, 8)
    const int*   perm = (const int*)  d_in[1];   // perm      (32, 8)
    const float* mw0  = (const float*)d_in[2];   // meanw0    (32, 1, 25)
    const float* mwr  = (const float*)d_in[3];   // meanw_rest(7, 32, 25, 25)
    const float* vw0  = (const float*)d_in[4];   // varw0     (32, 1, 25)
    const float* vwr  = (const float*)d_in[5];   // varw_rest (7, 32, 25, 25)
    const float* pp   = (const float*)d_in[6];   // post_prec (32,)
    float* out = (float*)d_out;                  // (N, 2) float32

    double bn_d[25], sc2_d[25];
    compute_binom_d(bn_d);
    compute_sc2_d(bn_d, sc2_d);

    Binom bn = {};
    Sc2   sc = {};
    for (int k = 0; k < 25; k++) {
        bn.b[k] = (float)bn_d[k];
        sc.v[k] = (float)sc2_d[k];
    }

    bern_prep_kernel<<<(N_DIM * N_PTS) / 256, 256>>>(X, out, bn);

    dim3 grid(N_PTS / 256, N_PERM, 2);
    bern_chain_kernel<<<grid, 128>>>(perm, mw0, mwr, vw0, vwr, pp, out, sc);
}